// round 5
// baseline (speedup 1.0000x reference)
#include <cuda_runtime.h>
#include <cuda_bf16.h>
#include <math.h>
#include <stdint.h>

// Problem constants
#define TOK   100352          // B * H * W = 32*56*56  (= 2048 windows * 49 tokens)
#define CCH   384
#define HID3  1152
#define HIDM  1536
#define NWIN  2048            // B * 64
#define NHEAD 12

// ---------------- scratch (device globals; no allocation allowed) ------------
__device__ float g_h  [(size_t)TOK * CCH];
__device__ float g_big[(size_t)TOK * HIDM];
__device__ float g_y  [(size_t)TOK * CCH];

// map windowed row t -> flat (b*3136 + h*56 + w) index in the UNSHIFTED image
__device__ __forceinline__ int winrow_to_dst(int t) {
    int n  = t % 49;
    int w_ = t / 49;
    int b  = w_ >> 6;
    int nw = w_ & 63;
    int wh = nw >> 3, ww = nw & 7;
    int r = n / 7, c = n % 7;
    int h = wh * 7 + r + 3; if (h >= 56) h -= 56;
    int w = ww * 7 + c + 3; if (w >= 56) w -= 56;
    return b * 3136 + h * 56 + w;
}

__device__ __forceinline__ void cp16(uint32_t s, const float* g) {
    asm volatile("cp.async.ca.shared.global [%0], [%1], 16;" :: "r"(s), "l"(g));
}

// ---------------- LayerNorm (+optional shift/window gather) ------------------
__global__ void ln_kernel(const float* __restrict__ x, const float* __restrict__ g,
                          const float* __restrict__ b, float* __restrict__ out,
                          int windowed)
{
    int t = blockIdx.x;
    size_t src;
    if (windowed) {
        int n  = t % 49;
        int w_ = t / 49;
        int batch = w_ >> 6;
        int nw = w_ & 63;
        int wh = nw >> 3, ww = nw & 7;
        int r = n / 7, c = n % 7;
        int h  = wh * 7 + r + 3; if (h  >= 56) h  -= 56;
        int wc = ww * 7 + c + 3; if (wc >= 56) wc -= 56;
        src = ((size_t)batch * 3136 + h * 56 + wc) * CCH;
    } else {
        src = (size_t)t * CCH;
    }
    int tid = threadIdx.x;
    float v0 = x[src + tid];
    float v1 = x[src + tid + 128];
    float v2 = x[src + tid + 256];
    float s  = v0 + v1 + v2;
    float ss = v0 * v0 + v1 * v1 + v2 * v2;
    #pragma unroll
    for (int o = 16; o; o >>= 1) {
        s  += __shfl_xor_sync(0xffffffffu, s,  o);
        ss += __shfl_xor_sync(0xffffffffu, ss, o);
    }
    __shared__ float sh_s[4], sh_q[4];
    int wid = tid >> 5, lane = tid & 31;
    if (lane == 0) { sh_s[wid] = s; sh_q[wid] = ss; }
    __syncthreads();
    float ts = sh_s[0] + sh_s[1] + sh_s[2] + sh_s[3];
    float tq = sh_q[0] + sh_q[1] + sh_q[2] + sh_q[3];
    float mean = ts * (1.0f / 384.0f);
    float var  = tq * (1.0f / 384.0f) - mean * mean;
    float inv  = rsqrtf(var + 1e-5f);
    size_t dst = (size_t)t * CCH;
    out[dst + tid]       = (v0 - mean) * inv * g[tid]       + b[tid];
    out[dst + tid + 128] = (v1 - mean) * inv * g[tid + 128] + b[tid + 128];
    out[dst + tid + 256] = (v2 - mean) * inv * g[tid + 256] + b[tid + 256];
}

// ---------------- tf32 tensor-core GEMM, 3-stage cp.async, ldmatrix A --------
// C[M,N] = A[M,K] @ B[K,N]
// Block 256x128x16, 256 thr = 8 warps (4M x 2N), warp 64x64 = 4x8 m16n8k8.
#define AS_STR 20
#define BS_STR 136
#define AS_TSZ (256 * AS_STR)
#define BS_TSZ (16 * BS_STR)
#define SMEM_BYTES ((AS_TSZ + BS_TSZ) * 3 * 4)
template<int MODE>
__global__ void __launch_bounds__(256, 1)
gemm_kernel(const float* __restrict__ A, const float* __restrict__ B,
            float* __restrict__ C, const float* __restrict__ bias,
            const float* __restrict__ resid, int M, int N, int K)
{
    extern __shared__ __align__(16) float smem[];
    float* AsBase = smem;                       // 3 stages of 256x20
    float* BsBase = smem + 3 * AS_TSZ;          // 3 stages of 16x136

    int tid  = threadIdx.x;
    int wid  = tid >> 5, lane = tid & 31;
    int wm   = wid & 3, wn = wid >> 2;          // 4 x 2 warp grid
    int grp  = lane >> 2, tig = lane & 3;
    int m0   = blockIdx.y * 256, n0 = blockIdx.x * 128;

    float acc[4][8][4];
    #pragma unroll
    for (int mi = 0; mi < 4; mi++)
        #pragma unroll
        for (int ni = 0; ni < 8; ni++)
            #pragma unroll
            for (int r = 0; r < 4; r++) acc[mi][ni][r] = 0.0f;

    // fill mappings
    int a_row = tid >> 2, a_kc = (tid & 3) << 2;     // rows +0/64/128/192
    int b_row = tid >> 5, b_nc = (tid & 31) << 2;    // rows +0/+8

    uint32_t sA0 = (uint32_t)__cvta_generic_to_shared(AsBase);
    uint32_t sB0 = (uint32_t)__cvta_generic_to_shared(BsBase);

    const float* gA = A + (size_t)(m0 + a_row) * K + a_kc;
    const float* gB = B + (size_t)b_row * N + n0 + b_nc;

    uint32_t a_lm_off = (uint32_t)(((wm * 64 + (lane & 15)) * AS_STR + ((lane >> 4) << 2)) * 4);

    int T = K >> 4;

    // fill stage st with slab t
    auto fill = [&](int st, int t) {
        uint32_t sA = sA0 + (uint32_t)(st * AS_TSZ * 4);
        uint32_t sB = sB0 + (uint32_t)(st * BS_TSZ * 4);
        const float* ga = gA + t * 16;
        const float* gb = gB + (size_t)t * 16 * N;
        #pragma unroll
        for (int r = 0; r < 4; r++)
            cp16(sA + (uint32_t)(((a_row + 64 * r) * AS_STR + a_kc) * 4),
                 ga + (size_t)(64 * r) * K);
        #pragma unroll
        for (int r = 0; r < 2; r++)
            cp16(sB + (uint32_t)(((b_row + 8 * r) * BS_STR + b_nc) * 4),
                 gb + (size_t)(8 * r) * N);
        asm volatile("cp.async.commit_group;");
    };

    fill(0, 0);
    if (T > 1) fill(1, 1);

    for (int t = 0; t < T; t++) {
        if (t + 1 < T) asm volatile("cp.async.wait_group 1;");
        else           asm volatile("cp.async.wait_group 0;");
        __syncthreads();

        int cur = t % 3;
        uint32_t aStage = sA0 + (uint32_t)(cur * AS_TSZ * 4) + a_lm_off;
        const float* bsm = BsBase + cur * BS_TSZ;

        #pragma unroll
        for (int ks = 0; ks < 16; ks += 8) {
            uint32_t af[4][4];
            #pragma unroll
            for (int mi = 0; mi < 4; mi++) {
                uint32_t ad = aStage + (uint32_t)((mi * 16 * AS_STR + ks) * 4);
                asm volatile("ldmatrix.sync.aligned.m8n8.x4.b16 {%0,%1,%2,%3}, [%4];"
                             : "=r"(af[mi][0]), "=r"(af[mi][1]),
                               "=r"(af[mi][2]), "=r"(af[mi][3]) : "r"(ad));
            }
            #pragma unroll
            for (int ni = 0; ni < 8; ni++) {
                int c0 = (ks + tig) * BS_STR + wn * 64 + ni * 8 + grp;
                uint32_t b0 = __float_as_uint(bsm[c0]);
                uint32_t b1 = __float_as_uint(bsm[c0 + 4 * BS_STR]);
                #pragma unroll
                for (int mi = 0; mi < 4; mi++) {
                    float* d = acc[mi][ni];
                    asm volatile(
                        "mma.sync.aligned.m16n8k8.row.col.f32.tf32.tf32.f32 "
                        "{%0,%1,%2,%3},{%4,%5,%6,%7},{%8,%9},{%0,%1,%2,%3};"
                        : "+f"(d[0]), "+f"(d[1]), "+f"(d[2]), "+f"(d[3])
                        : "r"(af[mi][0]), "r"(af[mi][1]), "r"(af[mi][2]), "r"(af[mi][3]),
                          "r"(b0), "r"(b1));
                }
            }
        }
        if (t + 2 < T) fill((t + 2) % 3, t + 2);
    }

    // ---- epilogue ----
    #pragma unroll
    for (int mi = 0; mi < 4; mi++) {
        int r0 = m0 + wm * 64 + mi * 16 + grp;
        int r1 = r0 + 8;
        int dst0 = 0, dst1 = 0;
        if (MODE == 1) { dst0 = winrow_to_dst(r0); dst1 = winrow_to_dst(r1); }
        #pragma unroll
        for (int ni = 0; ni < 8; ni++) {
            int col = n0 + wn * 64 + ni * 8 + tig * 2;
            float b0 = bias[col], b1 = bias[col + 1];
            float v00 = acc[mi][ni][0] + b0, v01 = acc[mi][ni][1] + b1;
            float v10 = acc[mi][ni][2] + b0, v11 = acc[mi][ni][3] + b1;
            if (MODE == 0) {
                *(float2*)&C[(size_t)r0 * N + col] = make_float2(v00, v01);
                *(float2*)&C[(size_t)r1 * N + col] = make_float2(v10, v11);
            } else if (MODE == 1) {
                size_t o0 = (size_t)dst0 * CCH + col;
                size_t o1 = (size_t)dst1 * CCH + col;
                *(float2*)&C[o0] = make_float2(resid[o0] + v00, resid[o0 + 1] + v01);
                *(float2*)&C[o1] = make_float2(resid[o1] + v10, resid[o1 + 1] + v11);
            } else if (MODE == 2) {
                const float is2 = 0.70710678118654752f;
                v00 = 0.5f * v00 * (1.0f + erff(v00 * is2));
                v01 = 0.5f * v01 * (1.0f + erff(v01 * is2));
                v10 = 0.5f * v10 * (1.0f + erff(v10 * is2));
                v11 = 0.5f * v11 * (1.0f + erff(v11 * is2));
                *(float2*)&C[(size_t)r0 * N + col] = make_float2(v00, v01);
                *(float2*)&C[(size_t)r1 * N + col] = make_float2(v10, v11);
            } else {
                size_t o0 = (size_t)r0 * CCH + col;
                size_t o1 = (size_t)r1 * CCH + col;
                *(float2*)&C[o0] = make_float2(resid[o0] + v00, resid[o0 + 1] + v01);
                *(float2*)&C[o1] = make_float2(resid[o1] + v10, resid[o1 + 1] + v11);
            }
        }
    }
}

// ---------------- windowed attention: one block per (window, head) -----------
__global__ void __launch_bounds__(256)
attn_kernel(const float* __restrict__ qkv, const float* __restrict__ rpb,
            float* __restrict__ out)
{
    int blk  = blockIdx.x;
    int head = blk % NHEAD;
    int win  = blk / NHEAD;

    __shared__ float Qs[49][32], Ks[49][32], Vs[49][32];
    __shared__ float S[49][52];
    __shared__ int   regio[49];

    int tid = threadIdx.x;
    const float scale = 0.17677669529663687f;
    size_t base = (size_t)win * 49 * HID3 + head * 32;

    for (int idx = tid; idx < 49 * 32; idx += 256) {
        int n = idx >> 5, d = idx & 31;
        size_t rb = base + (size_t)n * HID3 + d;
        Qs[n][d] = qkv[rb] * scale;
        Ks[n][d] = qkv[rb + 384];
        Vs[n][d] = qkv[rb + 768];
    }
    if (tid < 49) {
        int nw = win & 63;
        int wh = nw >> 3, ww = nw & 7;
        int r = tid / 7, c = tid % 7;
        int hh = wh * 7 + r, wg = ww * 7 + c;
        int rh = hh < 49 ? 0 : (hh < 53 ? 1 : 2);
        int rw = wg < 49 ? 0 : (wg < 53 ? 1 : 2);
        regio[tid] = rh * 3 + rw;
    }
    __syncthreads();

    for (int idx = tid; idx < 49 * 49; idx += 256) {
        int i = idx / 49, j = idx % 49;
        float s = 0.0f;
        #pragma unroll
        for (int d = 0; d < 32; d++) s += Qs[i][d] * Ks[j][d];
        int ri = i / 7, ci = i % 7, rj = j / 7, cj = j % 7;
        int rel = (ri - rj + 6) * 13 + (ci - cj + 6);
        s += rpb[rel * NHEAD + head];
        if (regio[i] != regio[j]) s -= 100.0f;
        S[i][j] = s;
    }
    __syncthreads();

    int wid = tid >> 5, lane = tid & 31;
    for (int i = wid; i < 49; i += 8) {
        float v0 = S[i][lane];
        float v1 = (lane + 32 < 49) ? S[i][lane + 32] : -1e30f;
        float m = fmaxf(v0, v1);
        #pragma unroll
        for (int o = 16; o; o >>= 1) m = fmaxf(m, __shfl_xor_sync(0xffffffffu, m, o));
        float e0 = __expf(v0 - m);
        float e1 = (lane + 32 < 49) ? __expf(v1 - m) : 0.0f;
        float sum = e0 + e1;
        #pragma unroll
        for (int o = 16; o; o >>= 1) sum += __shfl_xor_sync(0xffffffffu, sum, o);
        float inv = 1.0f / sum;
        S[i][lane] = e0 * inv;
        if (lane + 32 < 49) S[i][lane + 32] = e1 * inv;
    }
    __syncthreads();

    for (int idx = tid; idx < 49 * 32; idx += 256) {
        int i = idx >> 5, d = idx & 31;
        float o = 0.0f;
        #pragma unroll
        for (int j = 0; j < 49; j++) o += S[i][j] * Vs[j][d];
        out[((size_t)win * 49 + i) * CCH + head * 32 + d] = o;
    }
}

// ---------------------------------- driver -----------------------------------
extern "C" void kernel_launch(void* const* d_in, const int* in_sizes, int n_in,
                              void* d_out, int out_size)
{
    const float* x      = (const float*)d_in[0];
    const float* g1     = (const float*)d_in[1];
    const float* b1     = (const float*)d_in[2];
    const float* w_qkv  = (const float*)d_in[3];
    const float* b_qkv  = (const float*)d_in[4];
    const float* w_proj = (const float*)d_in[5];
    const float* b_proj = (const float*)d_in[6];
    const float* rpb    = (const float*)d_in[7];
    const float* g2     = (const float*)d_in[8];
    const float* b2     = (const float*)d_in[9];
    const float* w1     = (const float*)d_in[10];
    const float* bm1    = (const float*)d_in[11];
    const float* w2     = (const float*)d_in[12];
    const float* bm2    = (const float*)d_in[13];
    float* out = (float*)d_out;

    float *h, *big, *y;
    cudaGetSymbolAddress((void**)&h,   g_h);
    cudaGetSymbolAddress((void**)&big, g_big);
    cudaGetSymbolAddress((void**)&y,   g_y);

    cudaFuncSetAttribute(gemm_kernel<0>, cudaFuncAttributeMaxDynamicSharedMemorySize, SMEM_BYTES);
    cudaFuncSetAttribute(gemm_kernel<1>, cudaFuncAttributeMaxDynamicSharedMemorySize, SMEM_BYTES);
    cudaFuncSetAttribute(gemm_kernel<2>, cudaFuncAttributeMaxDynamicSharedMemorySize, SMEM_BYTES);
    cudaFuncSetAttribute(gemm_kernel<3>, cudaFuncAttributeMaxDynamicSharedMemorySize, SMEM_BYTES);

    // 1) LN1 + roll(-3,-3) + window partition -> h [100352, 384]
    ln_kernel<<<TOK, 128>>>(x, g1, b1, h, 1);

    // 2) QKV: h @ w_qkv + b_qkv -> big [100352, 1152]
    gemm_kernel<0><<<dim3(HID3 / 128, TOK / 256), 256, SMEM_BYTES>>>(
        h, w_qkv, big, b_qkv, nullptr, TOK, HID3, CCH);

    // 3) attention per (window, head) -> h [100352, 384]
    attn_kernel<<<NWIN * NHEAD, 256>>>(big, rpb, h);

    // 4) proj + window reverse + roll(+3,+3) + residual(x) -> y [100352, 384]
    gemm_kernel<1><<<dim3(CCH / 128, TOK / 256), 256, SMEM_BYTES>>>(
        h, w_proj, y, b_proj, x, TOK, CCH, CCH);

    // 5) LN2 -> h
    ln_kernel<<<TOK, 128>>>(y, g2, b2, h, 0);

    // 6) fc1 + exact GELU -> big [100352, 1536]
    gemm_kernel<2><<<dim3(HIDM / 128, TOK / 256), 256, SMEM_BYTES>>>(
        h, w1, big, bm1, nullptr, TOK, HIDM, CCH);

    // 7) fc2 + residual(y) -> out
    gemm_kernel<3><<<dim3(CCH / 128, TOK / 256), 256, SMEM_BYTES>>>(
        big, w2, out, bm2, y, TOK, CCH, HIDM);
}

// round 9
// speedup vs baseline: 1.1870x; 1.1870x over previous
#include <cuda_runtime.h>
#include <cuda_fp16.h>
#include <math.h>
#include <stdint.h>

// Problem constants
#define TOK   100352          // B * H * W = 32*56*56  (= 2048 windows * 49 tokens)
#define CCH   384
#define HID3  1152
#define HIDM  1536
#define NWIN  2048            // B * 64
#define NHEAD 12

// ---------------- scratch (device globals; no allocation allowed) ------------
__device__ __half g_h  [(size_t)TOK * CCH];    // fp16 intermediates (GEMM A inputs)
__device__ __half g_big[(size_t)TOK * HIDM];   // qkv / mlp hidden (fp16)
__device__ float  g_y  [(size_t)TOK * CCH];    // fp32 residual after attention
__device__ __half g_wT [1769472];              // fp16 transposed weights

#define OFF_QKVT  0
#define OFF_PROJT 442368
#define OFF_W1T   589824
#define OFF_W2T   1179648

// map windowed row t -> flat (b*3136 + h*56 + w) index in the UNSHIFTED image
__device__ __forceinline__ int winrow_to_dst(int t) {
    int n  = t % 49;
    int w_ = t / 49;
    int b  = w_ >> 6;
    int nw = w_ & 63;
    int wh = nw >> 3, ww = nw & 7;
    int r = n / 7, c = n % 7;
    int h = wh * 7 + r + 3; if (h >= 56) h -= 56;
    int w = ww * 7 + c + 3; if (w >= 56) w -= 56;
    return b * 3136 + h * 56 + w;
}

__device__ __forceinline__ void cp16(uint32_t s, const void* g) {
    asm volatile("cp.async.ca.shared.global [%0], [%1], 16;" :: "r"(s), "l"(g));
}

// ---------------- weight transpose+cvt: in f32[K,N] -> out f16[N,K] ----------
__global__ void transpose_kernel(const float* __restrict__ in, __half* __restrict__ out,
                                 int K, int N)
{
    __shared__ float t[32][33];
    int k0 = blockIdx.y * 32, n0 = blockIdx.x * 32;
    int tx = threadIdx.x & 31, ty = threadIdx.x >> 5;   // 256 thr: ty 0..7
    #pragma unroll
    for (int i = 0; i < 32; i += 8)
        t[ty + i][tx] = in[(size_t)(k0 + ty + i) * N + n0 + tx];
    __syncthreads();
    #pragma unroll
    for (int i = 0; i < 32; i += 8)
        out[(size_t)(n0 + ty + i) * K + k0 + tx] = __float2half(t[tx][ty + i]);
}

// ---------------- LayerNorm (+optional shift/window gather), fp16 out --------
__global__ void ln_kernel(const float* __restrict__ x, const float* __restrict__ g,
                          const float* __restrict__ b, __half* __restrict__ out,
                          int windowed)
{
    int t = blockIdx.x;
    size_t src;
    if (windowed) {
        int n  = t % 49;
        int w_ = t / 49;
        int batch = w_ >> 6;
        int nw = w_ & 63;
        int wh = nw >> 3, ww = nw & 7;
        int r = n / 7, c = n % 7;
        int h  = wh * 7 + r + 3; if (h  >= 56) h  -= 56;
        int wc = ww * 7 + c + 3; if (wc >= 56) wc -= 56;
        src = ((size_t)batch * 3136 + h * 56 + wc) * CCH;
    } else {
        src = (size_t)t * CCH;
    }
    int tid = threadIdx.x;
    float v0 = x[src + tid];
    float v1 = x[src + tid + 128];
    float v2 = x[src + tid + 256];
    float s  = v0 + v1 + v2;
    float ss = v0 * v0 + v1 * v1 + v2 * v2;
    #pragma unroll
    for (int o = 16; o; o >>= 1) {
        s  += __shfl_xor_sync(0xffffffffu, s,  o);
        ss += __shfl_xor_sync(0xffffffffu, ss, o);
    }
    __shared__ float sh_s[4], sh_q[4];
    int wid = tid >> 5, lane = tid & 31;
    if (lane == 0) { sh_s[wid] = s; sh_q[wid] = ss; }
    __syncthreads();
    float ts = sh_s[0] + sh_s[1] + sh_s[2] + sh_s[3];
    float tq = sh_q[0] + sh_q[1] + sh_q[2] + sh_q[3];
    float mean = ts * (1.0f / 384.0f);
    float var  = tq * (1.0f / 384.0f) - mean * mean;
    float inv  = rsqrtf(var + 1e-5f);
    size_t dst = (size_t)t * CCH;
    out[dst + tid]       = __float2half((v0 - mean) * inv * g[tid]       + b[tid]);
    out[dst + tid + 128] = __float2half((v1 - mean) * inv * g[tid + 128] + b[tid + 128]);
    out[dst + tid + 256] = __float2half((v2 - mean) * inv * g[tid + 256] + b[tid + 256]);
}

// ---------------- fp16 tensor-core GEMM (m16n8k16) + fused epilogues ---------
// C[M,N] = A[M,K] @ BT[N,K]^T   (A fp16 K-major, BT fp16 K-major)
// Block 128x128, k-slab 32, 2-stage cp.async.  8 warps (2M x 4N), warp 64x32.
#define HSTR 40
#define HTSZ (128 * HSTR)     // halves per tile
template<int MODE>
__global__ void __launch_bounds__(256, 2)
gemm_h(const __half* __restrict__ A, const __half* __restrict__ BT,
       void* __restrict__ Cv, const float* __restrict__ bias,
       const float* __restrict__ resid, int M, int N, int K)
{
    __shared__ __align__(16) __half As[2][HTSZ];
    __shared__ __align__(16) __half Bs[2][HTSZ];

    __half* Ch = (__half*)Cv;
    float*  Cf = (float*)Cv;

    int tid  = threadIdx.x;
    int wid  = tid >> 5, lane = tid & 31;
    int wm   = wid & 1, wn = wid >> 1;                 // 2 x 4 warp grid
    int grp  = lane >> 2, tig = lane & 3;
    int m0   = blockIdx.y * 128, n0 = blockIdx.x * 128;

    float acc[4][4][4];
    #pragma unroll
    for (int mi = 0; mi < 4; mi++)
        #pragma unroll
        for (int ni = 0; ni < 4; ni++)
            #pragma unroll
            for (int r = 0; r < 4; r++) acc[mi][ni][r] = 0.0f;

    uint32_t sA0 = (uint32_t)__cvta_generic_to_shared(&As[0][0]);
    uint32_t sB0 = (uint32_t)__cvta_generic_to_shared(&Bs[0][0]);

    // fill mapping: 512 16B-chunks per tile; 256 thr x 2
    int fr = tid >> 1, fo = tid & 1;

    auto fill = [&](int slab) {
        int st = slab & 1;
        int k0 = slab * 32;
        #pragma unroll
        for (int i = 0; i < 2; i++) {
            int off = fo + i * 2;                      // 0..3 (16B units)
            uint32_t d = (uint32_t)(fr * 80 + off * 16);
            cp16(sA0 + st * (HTSZ * 2) + d, A  + (size_t)(m0 + fr) * K + k0 + off * 8);
            cp16(sB0 + st * (HTSZ * 2) + d, BT + (size_t)(n0 + fr) * K + k0 + off * 8);
        }
        asm volatile("cp.async.commit_group;");
    };

    int T = K >> 5;
    fill(0);

    // ldmatrix lane offsets (bytes)
    uint32_t aoff = (uint32_t)((wm * 64 + (lane & 15)) * 80 + ((lane >> 4) << 4));
    uint32_t boff = (uint32_t)((wn * 32 + ((lane >> 4) << 3) + (lane & 7)) * 80
                               + (((lane >> 3) & 1) << 4));

    for (int t = 0; t < T; t++) {
        if (t + 1 < T) { fill(t + 1); asm volatile("cp.async.wait_group 1;"); }
        else           {              asm volatile("cp.async.wait_group 0;"); }
        __syncthreads();

        int cur = t & 1;
        uint32_t aS = sA0 + cur * (HTSZ * 2);
        uint32_t bS = sB0 + cur * (HTSZ * 2);

        #pragma unroll
        for (int ks = 0; ks < 2; ks++) {               // two k16 steps (bytes 0 / 32)
            uint32_t af[4][4], bf[4][2];
            #pragma unroll
            for (int mi = 0; mi < 4; mi++) {
                uint32_t ad = aS + aoff + (uint32_t)(mi * 16 * 80 + ks * 32);
                asm volatile("ldmatrix.sync.aligned.m8n8.x4.shared.b16 {%0,%1,%2,%3},[%4];"
                             : "=r"(af[mi][0]), "=r"(af[mi][1]),
                               "=r"(af[mi][2]), "=r"(af[mi][3]) : "r"(ad));
            }
            #pragma unroll
            for (int nj = 0; nj < 2; nj++) {
                uint32_t bd = bS + boff + (uint32_t)(nj * 16 * 80 + ks * 32);
                asm volatile("ldmatrix.sync.aligned.m8n8.x4.shared.b16 {%0,%1,%2,%3},[%4];"
                             : "=r"(bf[nj*2][0]), "=r"(bf[nj*2][1]),
                               "=r"(bf[nj*2+1][0]), "=r"(bf[nj*2+1][1]) : "r"(bd));
            }
            #pragma unroll
            for (int mi = 0; mi < 4; mi++)
                #pragma unroll
                for (int ni = 0; ni < 4; ni++) {
                    float* d = acc[mi][ni];
                    asm volatile(
                        "mma.sync.aligned.m16n8k16.row.col.f32.f16.f16.f32 "
                        "{%0,%1,%2,%3},{%4,%5,%6,%7},{%8,%9},{%0,%1,%2,%3};"
                        : "+f"(d[0]), "+f"(d[1]), "+f"(d[2]), "+f"(d[3])
                        : "r"(af[mi][0]), "r"(af[mi][1]), "r"(af[mi][2]), "r"(af[mi][3]),
                          "r"(bf[ni][0]), "r"(bf[ni][1]));
                }
        }
        __syncthreads();
    }

    // ---- epilogue ----
    #pragma unroll
    for (int mi = 0; mi < 4; mi++) {
        int r0 = m0 + wm * 64 + mi * 16 + grp;
        int r1 = r0 + 8;
        int dst0 = 0, dst1 = 0;
        if (MODE == 1) { dst0 = winrow_to_dst(r0); dst1 = winrow_to_dst(r1); }
        #pragma unroll
        for (int ni = 0; ni < 4; ni++) {
            int col = n0 + wn * 32 + ni * 8 + tig * 2;
            float b0 = bias[col], b1 = bias[col + 1];
            float v00 = acc[mi][ni][0] + b0, v01 = acc[mi][ni][1] + b1;
            float v10 = acc[mi][ni][2] + b0, v11 = acc[mi][ni][3] + b1;
            if (MODE == 0) {
                *(__half2*)&Ch[(size_t)r0 * N + col] = __floats2half2_rn(v00, v01);
                *(__half2*)&Ch[(size_t)r1 * N + col] = __floats2half2_rn(v10, v11);
            } else if (MODE == 1) {
                size_t o0 = (size_t)dst0 * CCH + col;
                size_t o1 = (size_t)dst1 * CCH + col;
                *(float2*)&Cf[o0] = make_float2(resid[o0] + v00, resid[o0 + 1] + v01);
                *(float2*)&Cf[o1] = make_float2(resid[o1] + v10, resid[o1 + 1] + v11);
            } else if (MODE == 2) {
                const float is2 = 0.70710678118654752f;
                v00 = 0.5f * v00 * (1.0f + erff(v00 * is2));
                v01 = 0.5f * v01 * (1.0f + erff(v01 * is2));
                v10 = 0.5f * v10 * (1.0f + erff(v10 * is2));
                v11 = 0.5f * v11 * (1.0f + erff(v11 * is2));
                *(__half2*)&Ch[(size_t)r0 * N + col] = __floats2half2_rn(v00, v01);
                *(__half2*)&Ch[(size_t)r1 * N + col] = __floats2half2_rn(v10, v11);
            } else {
                size_t o0 = (size_t)r0 * CCH + col;
                size_t o1 = (size_t)r1 * CCH + col;
                *(float2*)&Cf[o0] = make_float2(resid[o0] + v00, resid[o0 + 1] + v01);
                *(float2*)&Cf[o1] = make_float2(resid[o1] + v10, resid[o1 + 1] + v11);
            }
        }
    }
}

// ---------------- windowed attention: one block per (window, head) -----------
__global__ void __launch_bounds__(256)
attn_kernel(const __half* __restrict__ qkv, const float* __restrict__ rpb,
            __half* __restrict__ out)
{
    int blk  = blockIdx.x;
    int head = blk % NHEAD;
    int win  = blk / NHEAD;

    __shared__ float Qs[49][32], Ks[49][32], Vs[49][32];
    __shared__ float S[49][52];
    __shared__ int   regio[49];

    int tid = threadIdx.x;
    const float scale = 0.17677669529663687f;
    size_t base = (size_t)win * 49 * HID3 + head * 32;

    for (int idx = tid; idx < 49 * 32; idx += 256) {
        int n = idx >> 5, d = idx & 31;
        size_t rb = base + (size_t)n * HID3 + d;
        Qs[n][d] = __half2float(qkv[rb]) * scale;
        Ks[n][d] = __half2float(qkv[rb + 384]);
        Vs[n][d] = __half2float(qkv[rb + 768]);
    }
    if (tid < 49) {
        int nw = win & 63;
        int wh = nw >> 3, ww = nw & 7;
        int r = tid / 7, c = tid % 7;
        int hh = wh * 7 + r, wg = ww * 7 + c;
        int rh = hh < 49 ? 0 : (hh < 53 ? 1 : 2);
        int rw = wg < 49 ? 0 : (wg < 53 ? 1 : 2);
        regio[tid] = rh * 3 + rw;
    }
    __syncthreads();

    for (int idx = tid; idx < 49 * 49; idx += 256) {
        int i = idx / 49, j = idx % 49;
        float s = 0.0f;
        #pragma unroll
        for (int d = 0; d < 32; d++) s += Qs[i][d] * Ks[j][d];
        int ri = i / 7, ci = i % 7, rj = j / 7, cj = j % 7;
        int rel = (ri - rj + 6) * 13 + (ci - cj + 6);
        s += rpb[rel * NHEAD + head];
        if (regio[i] != regio[j]) s -= 100.0f;
        S[i][j] = s;
    }
    __syncthreads();

    int wid = tid >> 5, lane = tid & 31;
    for (int i = wid; i < 49; i += 8) {
        float v0 = S[i][lane];
        float v1 = (lane + 32 < 49) ? S[i][lane + 32] : -1e30f;
        float m = fmaxf(v0, v1);
        #pragma unroll
        for (int o = 16; o; o >>= 1) m = fmaxf(m, __shfl_xor_sync(0xffffffffu, m, o));
        float e0 = __expf(v0 - m);
        float e1 = (lane + 32 < 49) ? __expf(v1 - m) : 0.0f;
        float sum = e0 + e1;
        #pragma unroll
        for (int o = 16; o; o >>= 1) sum += __shfl_xor_sync(0xffffffffu, sum, o);
        float inv = 1.0f / sum;
        S[i][lane] = e0 * inv;
        if (lane + 32 < 49) S[i][lane + 32] = e1 * inv;
    }
    __syncthreads();

    for (int idx = tid; idx < 49 * 32; idx += 256) {
        int i = idx >> 5, d = idx & 31;
        float o = 0.0f;
        #pragma unroll
        for (int j = 0; j < 49; j++) o += S[i][j] * Vs[j][d];
        out[((size_t)win * 49 + i) * CCH + head * 32 + d] = __float2half(o);
    }
}

// ---------------------------------- driver -----------------------------------
extern "C" void kernel_launch(void* const* d_in, const int* in_sizes, int n_in,
                              void* d_out, int out_size)
{
    const float* x      = (const float*)d_in[0];
    const float* g1     = (const float*)d_in[1];
    const float* b1     = (const float*)d_in[2];
    const float* w_qkv  = (const float*)d_in[3];
    const float* b_qkv  = (const float*)d_in[4];
    const float* w_proj = (const float*)d_in[5];
    const float* b_proj = (const float*)d_in[6];
    const float* rpb    = (const float*)d_in[7];
    const float* g2     = (const float*)d_in[8];
    const float* b2     = (const float*)d_in[9];
    const float* w1     = (const float*)d_in[10];
    const float* bm1    = (const float*)d_in[11];
    const float* w2     = (const float*)d_in[12];
    const float* bm2    = (const float*)d_in[13];
    float* out = (float*)d_out;

    __half *h, *big, *wT;
    float *y;
    cudaGetSymbolAddress((void**)&h,   g_h);
    cudaGetSymbolAddress((void**)&big, g_big);
    cudaGetSymbolAddress((void**)&y,   g_y);
    cudaGetSymbolAddress((void**)&wT,  g_wT);

    // 0) transpose + cvt weights -> fp16 [N, K]
    transpose_kernel<<<dim3(HID3 / 32, CCH / 32), 256>>>(w_qkv,  wT + OFF_QKVT,  CCH,  HID3);
    transpose_kernel<<<dim3(CCH  / 32, CCH / 32), 256>>>(w_proj, wT + OFF_PROJT, CCH,  CCH);
    transpose_kernel<<<dim3(HIDM / 32, CCH / 32), 256>>>(w1,     wT + OFF_W1T,   CCH,  HIDM);
    transpose_kernel<<<dim3(CCH / 32, HIDM / 32), 256>>>(w2,     wT + OFF_W2T,   HIDM, CCH);

    // 1) LN1 + roll(-3,-3) + window partition -> h fp16 [100352, 384]
    ln_kernel<<<TOK, 128>>>(x, g1, b1, h, 1);

    // 2) QKV: h @ w_qkv + b_qkv -> big fp16 [100352, 1152]
    gemm_h<0><<<dim3(HID3 / 128, TOK / 128), 256>>>(
        h, wT + OFF_QKVT, big, b_qkv, nullptr, TOK, HID3, CCH);

    // 3) attention per (window, head) -> h fp16 [100352, 384]
    attn_kernel<<<NWIN * NHEAD, 256>>>(big, rpb, h);

    // 4) proj + window reverse + roll(+3,+3) + residual(x) -> y fp32
    gemm_h<1><<<dim3(CCH / 128, TOK / 128), 256>>>(
        h, wT + OFF_PROJT, y, b_proj, x, TOK, CCH, CCH);

    // 5) LN2 -> h fp16
    ln_kernel<<<TOK, 128>>>(y, g2, b2, h, 0);

    // 6) fc1 + exact GELU -> big fp16 [100352, 1536]
    gemm_h<2><<<dim3(HIDM / 128, TOK / 128), 256>>>(
        h, wT + OFF_W1T, big, bm1, nullptr, TOK, HIDM, CCH);

    // 7) fc2 + residual(y) -> out fp32
    gemm_h<3><<<dim3(CCH / 128, TOK / 128), 256>>>(
        big, wT + OFF_W2T, out, bm2, y, TOK, CCH, HIDM);
}

// round 11
// speedup vs baseline: 2.1940x; 1.8483x over previous
#include <cuda_runtime.h>
#include <cuda_fp16.h>
#include <math.h>
#include <stdint.h>

// Problem constants
#define TOK   100352          // B * H * W = 32*56*56  (= 2048 windows * 49 tokens)
#define CCH   384
#define HID3  1152
#define HIDM  1536
#define NWIN  2048            // B * 64
#define NHEAD 12

// ---------------- scratch (device globals; no allocation allowed) ------------
__device__ __half g_h  [(size_t)TOK * CCH];    // fp16 intermediates (GEMM A inputs)
__device__ __half g_big[(size_t)TOK * HIDM];   // qkv / mlp hidden (fp16)
__device__ float  g_y  [(size_t)TOK * CCH];    // fp32 residual after attention
__device__ __half g_wT [1769472];              // fp16 transposed weights

#define OFF_QKVT  0
#define OFF_PROJT 442368
#define OFF_W1T   589824
#define OFF_W2T   1179648

// map windowed row t -> flat (b*3136 + h*56 + w) index in the UNSHIFTED image
__device__ __forceinline__ int winrow_to_dst(int t) {
    int n  = t % 49;
    int w_ = t / 49;
    int b  = w_ >> 6;
    int nw = w_ & 63;
    int wh = nw >> 3, ww = nw & 7;
    int r = n / 7, c = n % 7;
    int h = wh * 7 + r + 3; if (h >= 56) h -= 56;
    int w = ww * 7 + c + 3; if (w >= 56) w -= 56;
    return b * 3136 + h * 56 + w;
}

__device__ __forceinline__ void cp16(uint32_t s, const void* g) {
    asm volatile("cp.async.ca.shared.global [%0], [%1], 16;" :: "r"(s), "l"(g));
}

// ---------------- weight transpose+cvt: in f32[K,N] -> out f16[N,K] ----------
__global__ void transpose_kernel(const float* __restrict__ in, __half* __restrict__ out,
                                 int K, int N)
{
    __shared__ float t[32][33];
    int k0 = blockIdx.y * 32, n0 = blockIdx.x * 32;
    int tx = threadIdx.x & 31, ty = threadIdx.x >> 5;   // 256 thr: ty 0..7
    #pragma unroll
    for (int i = 0; i < 32; i += 8)
        t[ty + i][tx] = in[(size_t)(k0 + ty + i) * N + n0 + tx];
    __syncthreads();
    #pragma unroll
    for (int i = 0; i < 32; i += 8)
        out[(size_t)(n0 + ty + i) * K + k0 + tx] = __float2half(t[tx][ty + i]);
}

// ---------------- LayerNorm (+optional shift/window gather), fp16 out --------
__global__ void ln_kernel(const float* __restrict__ x, const float* __restrict__ g,
                          const float* __restrict__ b, __half* __restrict__ out,
                          int windowed)
{
    int t = blockIdx.x;
    size_t src;
    if (windowed) {
        int n  = t % 49;
        int w_ = t / 49;
        int batch = w_ >> 6;
        int nw = w_ & 63;
        int wh = nw >> 3, ww = nw & 7;
        int r = n / 7, c = n % 7;
        int h  = wh * 7 + r + 3; if (h  >= 56) h  -= 56;
        int wc = ww * 7 + c + 3; if (wc >= 56) wc -= 56;
        src = ((size_t)batch * 3136 + h * 56 + wc) * CCH;
    } else {
        src = (size_t)t * CCH;
    }
    int tid = threadIdx.x;
    float v0 = x[src + tid];
    float v1 = x[src + tid + 128];
    float v2 = x[src + tid + 256];
    float s  = v0 + v1 + v2;
    float ss = v0 * v0 + v1 * v1 + v2 * v2;
    #pragma unroll
    for (int o = 16; o; o >>= 1) {
        s  += __shfl_xor_sync(0xffffffffu, s,  o);
        ss += __shfl_xor_sync(0xffffffffu, ss, o);
    }
    __shared__ float sh_s[4], sh_q[4];
    int wid = tid >> 5, lane = tid & 31;
    if (lane == 0) { sh_s[wid] = s; sh_q[wid] = ss; }
    __syncthreads();
    float ts = sh_s[0] + sh_s[1] + sh_s[2] + sh_s[3];
    float tq = sh_q[0] + sh_q[1] + sh_q[2] + sh_q[3];
    float mean = ts * (1.0f / 384.0f);
    float var  = tq * (1.0f / 384.0f) - mean * mean;
    float inv  = rsqrtf(var + 1e-5f);
    size_t dst = (size_t)t * CCH;
    out[dst + tid]       = __float2half((v0 - mean) * inv * g[tid]       + b[tid]);
    out[dst + tid + 128] = __float2half((v1 - mean) * inv * g[tid + 128] + b[tid + 128]);
    out[dst + tid + 256] = __float2half((v2 - mean) * inv * g[tid + 256] + b[tid + 256]);
}

// ---------------- fp16 tensor-core GEMM (m16n8k16) + fused epilogues ---------
#define HSTR 40
#define HTSZ (128 * HSTR)     // halves per tile
template<int MODE>
__global__ void __launch_bounds__(256, 2)
gemm_h(const __half* __restrict__ A, const __half* __restrict__ BT,
       void* __restrict__ Cv, const float* __restrict__ bias,
       const float* __restrict__ resid, int M, int N, int K)
{
    __shared__ __align__(16) __half As[2][HTSZ];
    __shared__ __align__(16) __half Bs[2][HTSZ];

    __half* Ch = (__half*)Cv;
    float*  Cf = (float*)Cv;

    int tid  = threadIdx.x;
    int wid  = tid >> 5, lane = tid & 31;
    int wm   = wid & 1, wn = wid >> 1;                 // 2 x 4 warp grid
    int grp  = lane >> 2, tig = lane & 3;
    int m0   = blockIdx.y * 128, n0 = blockIdx.x * 128;

    float acc[4][4][4];
    #pragma unroll
    for (int mi = 0; mi < 4; mi++)
        #pragma unroll
        for (int ni = 0; ni < 4; ni++)
            #pragma unroll
            for (int r = 0; r < 4; r++) acc[mi][ni][r] = 0.0f;

    uint32_t sA0 = (uint32_t)__cvta_generic_to_shared(&As[0][0]);
    uint32_t sB0 = (uint32_t)__cvta_generic_to_shared(&Bs[0][0]);

    int fr = tid >> 1, fo = tid & 1;

    auto fill = [&](int slab) {
        int st = slab & 1;
        int k0 = slab * 32;
        #pragma unroll
        for (int i = 0; i < 2; i++) {
            int off = fo + i * 2;                      // 0..3 (16B units)
            uint32_t d = (uint32_t)(fr * 80 + off * 16);
            cp16(sA0 + st * (HTSZ * 2) + d, A  + (size_t)(m0 + fr) * K + k0 + off * 8);
            cp16(sB0 + st * (HTSZ * 2) + d, BT + (size_t)(n0 + fr) * K + k0 + off * 8);
        }
        asm volatile("cp.async.commit_group;");
    };

    int T = K >> 5;
    fill(0);

    uint32_t aoff = (uint32_t)((wm * 64 + (lane & 15)) * 80 + ((lane >> 4) << 4));
    uint32_t boff = (uint32_t)((wn * 32 + ((lane >> 4) << 3) + (lane & 7)) * 80
                               + (((lane >> 3) & 1) << 4));

    for (int t = 0; t < T; t++) {
        if (t + 1 < T) { fill(t + 1); asm volatile("cp.async.wait_group 1;"); }
        else           {              asm volatile("cp.async.wait_group 0;"); }
        __syncthreads();

        int cur = t & 1;
        uint32_t aS = sA0 + cur * (HTSZ * 2);
        uint32_t bS = sB0 + cur * (HTSZ * 2);

        #pragma unroll
        for (int ks = 0; ks < 2; ks++) {
            uint32_t af[4][4], bf[4][2];
            #pragma unroll
            for (int mi = 0; mi < 4; mi++) {
                uint32_t ad = aS + aoff + (uint32_t)(mi * 16 * 80 + ks * 32);
                asm volatile("ldmatrix.sync.aligned.m8n8.x4.shared.b16 {%0,%1,%2,%3},[%4];"
                             : "=r"(af[mi][0]), "=r"(af[mi][1]),
                               "=r"(af[mi][2]), "=r"(af[mi][3]) : "r"(ad));
            }
            #pragma unroll
            for (int nj = 0; nj < 2; nj++) {
                uint32_t bd = bS + boff + (uint32_t)(nj * 16 * 80 + ks * 32);
                asm volatile("ldmatrix.sync.aligned.m8n8.x4.shared.b16 {%0,%1,%2,%3},[%4];"
                             : "=r"(bf[nj*2][0]), "=r"(bf[nj*2][1]),
                               "=r"(bf[nj*2+1][0]), "=r"(bf[nj*2+1][1]) : "r"(bd));
            }
            #pragma unroll
            for (int mi = 0; mi < 4; mi++)
                #pragma unroll
                for (int ni = 0; ni < 4; ni++) {
                    float* d = acc[mi][ni];
                    asm volatile(
                        "mma.sync.aligned.m16n8k16.row.col.f32.f16.f16.f32 "
                        "{%0,%1,%2,%3},{%4,%5,%6,%7},{%8,%9},{%0,%1,%2,%3};"
                        : "+f"(d[0]), "+f"(d[1]), "+f"(d[2]), "+f"(d[3])
                        : "r"(af[mi][0]), "r"(af[mi][1]), "r"(af[mi][2]), "r"(af[mi][3]),
                          "r"(bf[ni][0]), "r"(bf[ni][1]));
                }
        }
        __syncthreads();
    }

    // ---- epilogue ----
    #pragma unroll
    for (int mi = 0; mi < 4; mi++) {
        int r0 = m0 + wm * 64 + mi * 16 + grp;
        int r1 = r0 + 8;
        int dst0 = 0, dst1 = 0;
        if (MODE == 1) { dst0 = winrow_to_dst(r0); dst1 = winrow_to_dst(r1); }
        #pragma unroll
        for (int ni = 0; ni < 4; ni++) {
            int col = n0 + wn * 32 + ni * 8 + tig * 2;
            float b0 = bias[col], b1 = bias[col + 1];
            float v00 = acc[mi][ni][0] + b0, v01 = acc[mi][ni][1] + b1;
            float v10 = acc[mi][ni][2] + b0, v11 = acc[mi][ni][3] + b1;
            if (MODE == 0) {
                *(__half2*)&Ch[(size_t)r0 * N + col] = __floats2half2_rn(v00, v01);
                *(__half2*)&Ch[(size_t)r1 * N + col] = __floats2half2_rn(v10, v11);
            } else if (MODE == 1) {
                size_t o0 = (size_t)dst0 * CCH + col;
                size_t o1 = (size_t)dst1 * CCH + col;
                *(float2*)&Cf[o0] = make_float2(resid[o0] + v00, resid[o0 + 1] + v01);
                *(float2*)&Cf[o1] = make_float2(resid[o1] + v10, resid[o1 + 1] + v11);
            } else if (MODE == 2) {
                const float is2 = 0.70710678118654752f;
                v00 = 0.5f * v00 * (1.0f + erff(v00 * is2));
                v01 = 0.5f * v01 * (1.0f + erff(v01 * is2));
                v10 = 0.5f * v10 * (1.0f + erff(v10 * is2));
                v11 = 0.5f * v11 * (1.0f + erff(v11 * is2));
                *(__half2*)&Ch[(size_t)r0 * N + col] = __floats2half2_rn(v00, v01);
                *(__half2*)&Ch[(size_t)r1 * N + col] = __floats2half2_rn(v10, v11);
            } else {
                size_t o0 = (size_t)r0 * CCH + col;
                size_t o1 = (size_t)r1 * CCH + col;
                *(float2*)&Cf[o0] = make_float2(resid[o0] + v00, resid[o0 + 1] + v01);
                *(float2*)&Cf[o1] = make_float2(resid[o1] + v10, resid[o1 + 1] + v11);
            }
        }
    }
}

// ---------------- MMA windowed attention: one block per (window, head) -------
// 128 threads = 4 warps; warp w owns rows 16w..16w+15 (M padded 49->64).
// Smem: Qh/Kh/Vh fp16 [64][40] (80B rows, GEMM-proven ldmatrix layout),
//       S fp32 [64][56], Ph fp16 [64][72] aliased over dead Qh+Kh.
__global__ void __launch_bounds__(128)
attn_kernel(const __half* __restrict__ qkv, const float* __restrict__ rpb,
            __half* __restrict__ out)
{
    __shared__ __align__(16) unsigned char sm[15360 + 64 * 56 * 4];
    __shared__ int regio[49];

    __half* Qh = (__half*)sm;                 // [64][40]
    __half* Kh = (__half*)(sm + 5120);        // [64][40]
    __half* Vh = (__half*)(sm + 10240);       // [64][40]
    __half* Ph = (__half*)sm;                 // [64][72] alias over Qh+Kh (9216B < 10240B)
    float*  S  = (float*)(sm + 15360);        // [64][56]

    int blk  = blockIdx.x;
    int head = blk % NHEAD;
    int win  = blk / NHEAD;
    int tid  = threadIdx.x;
    int wid  = tid >> 5, lane = tid & 31;
    int grp  = lane >> 2, tig = lane & 3;
    const float scale = 0.17677669529663687f;   // 32^-0.5

    // ---- load Q/K/V (fp16 half2), zero V pad rows ----
    {
        const __half2* q2 = (const __half2*)(qkv + (size_t)win * 49 * HID3 + head * 32);
        __half2* Q2 = (__half2*)Qh;  __half2* K2 = (__half2*)Kh;  __half2* V2 = (__half2*)Vh;
        for (int idx = tid; idx < 49 * 16; idx += 128) {
            int n = idx >> 4, c = idx & 15;
            const __half2* row = q2 + (size_t)n * (HID3 / 2);
            Q2[n * 20 + c] = row[c];
            K2[n * 20 + c] = row[c + 192];   // +384 halves
            V2[n * 20 + c] = row[c + 384];   // +768 halves
        }
        for (int idx = tid; idx < 15 * 16; idx += 128) {   // V rows 49..63 = 0
            int n = 49 + (idx >> 4), c = idx & 15;
            V2[n * 20 + c] = __half2half2(__float2half(0.0f));
        }
        if (tid < 49) {
            int nw = win & 63;
            int wh = nw >> 3, ww = nw & 7;
            int r = tid / 7, c = tid % 7;
            int hh = wh * 7 + r, wg = ww * 7 + c;
            int rh = hh < 49 ? 0 : (hh < 53 ? 1 : 2);
            int rw = wg < 49 ? 0 : (wg < 53 ? 1 : 2);
            regio[tid] = rh * 3 + rw;
        }
    }
    __syncthreads();

    uint32_t sQ = (uint32_t)__cvta_generic_to_shared(Qh);
    uint32_t sK = (uint32_t)__cvta_generic_to_shared(Kh);
    uint32_t sV = (uint32_t)__cvta_generic_to_shared(Vh);
    uint32_t sP = (uint32_t)__cvta_generic_to_shared(Ph);

    // ---- S = Q K^T (M=64, N=56, K=32) ----
    {
        float acc[7][4];
        #pragma unroll
        for (int ni = 0; ni < 7; ni++)
            #pragma unroll
            for (int r = 0; r < 4; r++) acc[ni][r] = 0.0f;

        uint32_t aoff = (uint32_t)((wid * 16 + (lane & 15)) * 80 + ((lane >> 4) << 4));
        uint32_t boff = (uint32_t)((((lane >> 4) << 3) + (lane & 7)) * 80
                                   + (((lane >> 3) & 1) << 4));
        #pragma unroll
        for (int ks = 0; ks < 2; ks++) {
            uint32_t af[4], bf[8][2];
            asm volatile("ldmatrix.sync.aligned.m8n8.x4.shared.b16 {%0,%1,%2,%3},[%4];"
                         : "=r"(af[0]), "=r"(af[1]), "=r"(af[2]), "=r"(af[3])
                         : "r"(sQ + aoff + ks * 32));
            #pragma unroll
            for (int nj = 0; nj < 4; nj++) {
                uint32_t bd = sK + boff + (uint32_t)(nj * 16 * 80 + ks * 32);
                asm volatile("ldmatrix.sync.aligned.m8n8.x4.shared.b16 {%0,%1,%2,%3},[%4];"
                             : "=r"(bf[nj*2][0]), "=r"(bf[nj*2][1]),
                               "=r"(bf[nj*2+1][0]), "=r"(bf[nj*2+1][1]) : "r"(bd));
            }
            #pragma unroll
            for (int ni = 0; ni < 7; ni++) {
                float* d = acc[ni];
                asm volatile(
                    "mma.sync.aligned.m16n8k16.row.col.f32.f16.f16.f32 "
                    "{%0,%1,%2,%3},{%4,%5,%6,%7},{%8,%9},{%0,%1,%2,%3};"
                    : "+f"(d[0]), "+f"(d[1]), "+f"(d[2]), "+f"(d[3])
                    : "r"(af[0]), "r"(af[1]), "r"(af[2]), "r"(af[3]),
                      "r"(bf[ni][0]), "r"(bf[ni][1]));
            }
        }

        // epilogue: scale + rel-pos bias + shift mask -> S (valid i<49, j<49)
        int r0 = wid * 16 + grp, r1 = r0 + 8;
        #pragma unroll
        for (int ni = 0; ni < 7; ni++) {
            int c = ni * 8 + tig * 2;
            #pragma unroll
            for (int e = 0; e < 4; e++) {
                int i = (e < 2) ? r0 : r1;
                int j = c + (e & 1);
                if (i < 49 && j < 49) {
                    int ri = i / 7, ci = i % 7, rj = j / 7, cj = j % 7;
                    float s = acc[ni][e] * scale
                            + rpb[((ri - rj + 6) * 13 + (ci - cj + 6)) * NHEAD + head];
                    if (regio[i] != regio[j]) s -= 100.0f;
                    S[i * 56 + j] = s;
                }
            }
        }
    }
    __syncthreads();

    // ---- zero Ph (aliases Qh/Kh), then softmax rows -> Ph fp16 ----
    {
        __half2* P2 = (__half2*)Ph;
        for (int idx = tid; idx < 64 * 36; idx += 128)
            P2[idx] = __half2half2(__float2half(0.0f));
    }
    __syncthreads();
    for (int i = wid; i < 49; i += 4) {
        float v0 = S[i * 56 + lane];
        float v1 = (lane + 32 < 49) ? S[i * 56 + lane + 32] : -1e30f;
        float m = fmaxf(v0, v1);
        #pragma unroll
        for (int o = 16; o; o >>= 1) m = fmaxf(m, __shfl_xor_sync(0xffffffffu, m, o));
        float e0 = __expf(v0 - m);
        float e1 = (lane + 32 < 49) ? __expf(v1 - m) : 0.0f;
        float sum = e0 + e1;
        #pragma unroll
        for (int o = 16; o; o >>= 1) sum += __shfl_xor_sync(0xffffffffu, sum, o);
        float inv = 1.0f / sum;
        Ph[i * 72 + lane] = __float2half(e0 * inv);
        if (lane + 32 < 49) Ph[i * 72 + lane + 32] = __float2half(e1 * inv);
    }
    __syncthreads();

    // ---- O = P V  (M=64, N=32, K=64) ----
    {
        float acc[4][4];
        #pragma unroll
        for (int ni = 0; ni < 4; ni++)
            #pragma unroll
            for (int r = 0; r < 4; r++) acc[ni][r] = 0.0f;

        uint32_t aoff = (uint32_t)((wid * 16 + (lane & 15)) * 144 + ((lane >> 4) << 4));
        uint32_t voff = (uint32_t)((lane & 15) * 80 + ((lane >> 4) << 4));
        #pragma unroll
        for (int ks = 0; ks < 4; ks++) {
            uint32_t af[4], bf[4][2];
            asm volatile("ldmatrix.sync.aligned.m8n8.x4.shared.b16 {%0,%1,%2,%3},[%4];"
                         : "=r"(af[0]), "=r"(af[1]), "=r"(af[2]), "=r"(af[3])
                         : "r"(sP + aoff + ks * 32));
            #pragma unroll
            for (int np = 0; np < 2; np++) {
                uint32_t bd = sV + voff + (uint32_t)(ks * 16 * 80 + np * 32);
                asm volatile("ldmatrix.sync.aligned.m8n8.x4.trans.shared.b16 {%0,%1,%2,%3},[%4];"
                             : "=r"(bf[np*2][0]), "=r"(bf[np*2][1]),
                               "=r"(bf[np*2+1][0]), "=r"(bf[np*2+1][1]) : "r"(bd));
            }
            #pragma unroll
            for (int ni = 0; ni < 4; ni++) {
                float* d = acc[ni];
                asm volatile(
                    "mma.sync.aligned.m16n8k16.row.col.f32.f16.f16.f32 "
                    "{%0,%1,%2,%3},{%4,%5,%6,%7},{%8,%9},{%0,%1,%2,%3};"
                    : "+f"(d[0]), "+f"(d[1]), "+f"(d[2]), "+f"(d[3])
                    : "r"(af[0]), "r"(af[1]), "r"(af[2]), "r"(af[3]),
                      "r"(bf[ni][0]), "r"(bf[ni][1]));
            }
        }

        int r0 = wid * 16 + grp, r1 = r0 + 8;
        #pragma unroll
        for (int ni = 0; ni < 4; ni++) {
            int d = ni * 8 + tig * 2;
            if (r0 < 49)
                *(__half2*)&out[((size_t)win * 49 + r0) * CCH + head * 32 + d] =
                    __floats2half2_rn(acc[ni][0], acc[ni][1]);
            if (r1 < 49)
                *(__half2*)&out[((size_t)win * 49 + r1) * CCH + head * 32 + d] =
                    __floats2half2_rn(acc[ni][2], acc[ni][3]);
        }
    }
}

// ---------------------------------- driver -----------------------------------
extern "C" void kernel_launch(void* const* d_in, const int* in_sizes, int n_in,
                              void* d_out, int out_size)
{
    const float* x      = (const float*)d_in[0];
    const float* g1     = (const float*)d_in[1];
    const float* b1     = (const float*)d_in[2];
    const float* w_qkv  = (const float*)d_in[3];
    const float* b_qkv  = (const float*)d_in[4];
    const float* w_proj = (const float*)d_in[5];
    const float* b_proj = (const float*)d_in[6];
    const float* rpb    = (const float*)d_in[7];
    const float* g2     = (const float*)d_in[8];
    const float* b2     = (const float*)d_in[9];
    const float* w1     = (const float*)d_in[10];
    const float* bm1    = (const float*)d_in[11];
    const float* w2     = (const float*)d_in[12];
    const float* bm2    = (const float*)d_in[13];
    float* out = (float*)d_out;

    __half *h, *big, *wT;
    float *y;
    cudaGetSymbolAddress((void**)&h,   g_h);
    cudaGetSymbolAddress((void**)&big, g_big);
    cudaGetSymbolAddress((void**)&y,   g_y);
    cudaGetSymbolAddress((void**)&wT,  g_wT);

    // 0) transpose + cvt weights -> fp16 [N, K]
    transpose_kernel<<<dim3(HID3 / 32, CCH / 32), 256>>>(w_qkv,  wT + OFF_QKVT,  CCH,  HID3);
    transpose_kernel<<<dim3(CCH  / 32, CCH / 32), 256>>>(w_proj, wT + OFF_PROJT, CCH,  CCH);
    transpose_kernel<<<dim3(HIDM / 32, CCH / 32), 256>>>(w1,     wT + OFF_W1T,   CCH,  HIDM);
    transpose_kernel<<<dim3(CCH / 32, HIDM / 32), 256>>>(w2,     wT + OFF_W2T,   HIDM, CCH);

    // 1) LN1 + roll(-3,-3) + window partition -> h fp16 [100352, 384]
    ln_kernel<<<TOK, 128>>>(x, g1, b1, h, 1);

    // 2) QKV: h @ w_qkv + b_qkv -> big fp16 [100352, 1152]
    gemm_h<0><<<dim3(HID3 / 128, TOK / 128), 256>>>(
        h, wT + OFF_QKVT, big, b_qkv, nullptr, TOK, HID3, CCH);

    // 3) attention per (window, head) -> h fp16 [100352, 384]
    attn_kernel<<<NWIN * NHEAD, 128>>>(big, rpb, h);

    // 4) proj + window reverse + roll(+3,+3) + residual(x) -> y fp32
    gemm_h<1><<<dim3(CCH / 128, TOK / 128), 256>>>(
        h, wT + OFF_PROJT, y, b_proj, x, TOK, CCH, CCH);

    // 5) LN2 -> h fp16
    ln_kernel<<<TOK, 128>>>(y, g2, b2, h, 0);

    // 6) fc1 + exact GELU -> big fp16 [100352, 1536]
    gemm_h<2><<<dim3(HIDM / 128, TOK / 128), 256>>>(
        h, wT + OFF_W1T, big, bm1, nullptr, TOK, HIDM, CCH);

    // 7) fc2 + residual(y) -> out fp32
    gemm_h<3><<<dim3(CCH / 128, TOK / 128), 256>>>(
        big, wT + OFF_W2T, out, bm2, y, TOK, CCH, HIDM);
}

// round 14
// speedup vs baseline: 2.2191x; 1.0114x over previous
#include <cuda_runtime.h>
#include <cuda_fp16.h>
#include <math.h>
#include <stdint.h>

// Problem constants
#define TOK   100352          // B * H * W = 32*56*56  (= 2048 windows * 49 tokens)
#define CCH   384
#define HID3  1152
#define HIDM  1536
#define NWIN  2048            // B * 64
#define NHEAD 12

// ---------------- scratch (device globals; no allocation allowed) ------------
__device__ __half g_h  [(size_t)TOK * CCH];    // fp16 intermediates (GEMM A inputs)
__device__ __half g_big[(size_t)TOK * HIDM];   // qkv / mlp hidden (fp16)
__device__ float  g_y  [(size_t)TOK * CCH];    // fp32 residual after attention
__device__ __half g_wT [1769472];              // fp16 transposed weights

#define OFF_QKVT  0
#define OFF_PROJT 442368
#define OFF_W1T   589824
#define OFF_W2T   1179648

// map windowed row t -> flat (b*3136 + h*56 + w) index in the UNSHIFTED image
__device__ __forceinline__ int winrow_to_dst(int t) {
    int n  = t % 49;
    int w_ = t / 49;
    int b  = w_ >> 6;
    int nw = w_ & 63;
    int wh = nw >> 3, ww = nw & 7;
    int r = n / 7, c = n % 7;
    int h = wh * 7 + r + 3; if (h >= 56) h -= 56;
    int w = ww * 7 + c + 3; if (w >= 56) w -= 56;
    return b * 3136 + h * 56 + w;
}

__device__ __forceinline__ void cp16(uint32_t s, const void* g) {
    asm volatile("cp.async.ca.shared.global [%0], [%1], 16;" :: "r"(s), "l"(g));
}

// ---------------- weight transpose+cvt: in f32[K,N] -> out f16[N,K] ----------
__global__ void transpose_kernel(const float* __restrict__ in, __half* __restrict__ out,
                                 int K, int N)
{
    __shared__ float t[32][33];
    int k0 = blockIdx.y * 32, n0 = blockIdx.x * 32;
    int tx = threadIdx.x & 31, ty = threadIdx.x >> 5;   // 256 thr: ty 0..7
    #pragma unroll
    for (int i = 0; i < 32; i += 8)
        t[ty + i][tx] = in[(size_t)(k0 + ty + i) * N + n0 + tx];
    __syncthreads();
    #pragma unroll
    for (int i = 0; i < 32; i += 8)
        out[(size_t)(n0 + ty + i) * K + k0 + tx] = __float2half(t[tx][ty + i]);
}

// ---------------- LayerNorm (+optional shift/window gather), fp16 out --------
__global__ void ln_kernel(const float* __restrict__ x, const float* __restrict__ g,
                          const float* __restrict__ b, __half* __restrict__ out,
                          int windowed)
{
    int t = blockIdx.x;
    size_t src;
    if (windowed) {
        int n  = t % 49;
        int w_ = t / 49;
        int batch = w_ >> 6;
        int nw = w_ & 63;
        int wh = nw >> 3, ww = nw & 7;
        int r = n / 7, c = n % 7;
        int h  = wh * 7 + r + 3; if (h  >= 56) h  -= 56;
        int wc = ww * 7 + c + 3; if (wc >= 56) wc -= 56;
        src = ((size_t)batch * 3136 + h * 56 + wc) * CCH;
    } else {
        src = (size_t)t * CCH;
    }
    int tid = threadIdx.x;
    float v0 = x[src + tid];
    float v1 = x[src + tid + 128];
    float v2 = x[src + tid + 256];
    float s  = v0 + v1 + v2;
    float ss = v0 * v0 + v1 * v1 + v2 * v2;
    #pragma unroll
    for (int o = 16; o; o >>= 1) {
        s  += __shfl_xor_sync(0xffffffffu, s,  o);
        ss += __shfl_xor_sync(0xffffffffu, ss, o);
    }
    __shared__ float sh_s[4], sh_q[4];
    int wid = tid >> 5, lane = tid & 31;
    if (lane == 0) { sh_s[wid] = s; sh_q[wid] = ss; }
    __syncthreads();
    float ts = sh_s[0] + sh_s[1] + sh_s[2] + sh_s[3];
    float tq = sh_q[0] + sh_q[1] + sh_q[2] + sh_q[3];
    float mean = ts * (1.0f / 384.0f);
    float var  = tq * (1.0f / 384.0f) - mean * mean;
    float inv  = rsqrtf(var + 1e-5f);
    size_t dst = (size_t)t * CCH;
    out[dst + tid]       = __float2half((v0 - mean) * inv * g[tid]       + b[tid]);
    out[dst + tid + 128] = __float2half((v1 - mean) * inv * g[tid + 128] + b[tid + 128]);
    out[dst + tid + 256] = __float2half((v2 - mean) * inv * g[tid + 256] + b[tid + 256]);
}

// ---------------- fp16 tensor-core GEMM (m16n8k16) + fused epilogues ---------
// 3-stage cp.async ring, ONE __syncthreads per k-slab.
#define HSTR 40
#define HTSZ (128 * HSTR)            // halves per tile (5120 -> 10240 B)
#define STG_BYTES (HTSZ * 2 * 2)     // A + B per stage = 20480 B
#define GH_SMEM (3 * STG_BYTES)      // 61440 B
template<int MODE>
__global__ void __launch_bounds__(256, 2)
gemm_h(const __half* __restrict__ A, const __half* __restrict__ BT,
       void* __restrict__ Cv, const float* __restrict__ bias,
       const float* __restrict__ resid, int M, int N, int K)
{
    extern __shared__ __align__(16) unsigned char smraw[];

    __half* Ch = (__half*)Cv;
    float*  Cf = (float*)Cv;

    int tid  = threadIdx.x;
    int wid  = tid >> 5, lane = tid & 31;
    int wm   = wid & 1, wn = wid >> 1;                 // 2 x 4 warp grid
    int grp  = lane >> 2, tig = lane & 3;
    int m0   = blockIdx.y * 128, n0 = blockIdx.x * 128;

    float acc[4][4][4];
    #pragma unroll
    for (int mi = 0; mi < 4; mi++)
        #pragma unroll
        for (int ni = 0; ni < 4; ni++)
            #pragma unroll
            for (int r = 0; r < 4; r++) acc[mi][ni][r] = 0.0f;

    uint32_t s0 = (uint32_t)__cvta_generic_to_shared(smraw);

    int fr = tid >> 1, fo = tid & 1;

    auto fill = [&](int slab) {
        int st = slab % 3;
        uint32_t sA = s0 + (uint32_t)st * STG_BYTES;
        uint32_t sB = sA + HTSZ * 2;
        int k0 = slab * 32;
        #pragma unroll
        for (int i = 0; i < 2; i++) {
            int off = fo + i * 2;                      // 0..3 (16B units)
            uint32_t d = (uint32_t)(fr * 80 + off * 16);
            cp16(sA + d, A  + (size_t)(m0 + fr) * K + k0 + off * 8);
            cp16(sB + d, BT + (size_t)(n0 + fr) * K + k0 + off * 8);
        }
        asm volatile("cp.async.commit_group;");
    };

    int T = K >> 5;
    fill(0);
    if (T > 1) fill(1);

    uint32_t aoff = (uint32_t)((wm * 64 + (lane & 15)) * 80 + ((lane >> 4) << 4));
    uint32_t boff = (uint32_t)((wn * 32 + ((lane >> 4) << 3) + (lane & 7)) * 80
                               + (((lane >> 3) & 1) << 4));

    for (int t = 0; t < T; t++) {
        if (t + 1 < T) asm volatile("cp.async.wait_group 1;");
        else           asm volatile("cp.async.wait_group 0;");
        __syncthreads();
        if (t + 2 < T) fill(t + 2);    // writes stage last read at iter t-1: fenced above

        int cur = t % 3;
        uint32_t aS = s0 + (uint32_t)cur * STG_BYTES;
        uint32_t bS = aS + HTSZ * 2;

        #pragma unroll
        for (int ks = 0; ks < 2; ks++) {
            uint32_t af[4][4], bf[4][2];
            #pragma unroll
            for (int mi = 0; mi < 4; mi++) {
                uint32_t ad = aS + aoff + (uint32_t)(mi * 16 * 80 + ks * 32);
                asm volatile("ldmatrix.sync.aligned.m8n8.x4.shared.b16 {%0,%1,%2,%3},[%4];"
                             : "=r"(af[mi][0]), "=r"(af[mi][1]),
                               "=r"(af[mi][2]), "=r"(af[mi][3]) : "r"(ad));
            }
            #pragma unroll
            for (int nj = 0; nj < 2; nj++) {
                uint32_t bd = bS + boff + (uint32_t)(nj * 16 * 80 + ks * 32);
                asm volatile("ldmatrix.sync.aligned.m8n8.x4.shared.b16 {%0,%1,%2,%3},[%4];"
                             : "=r"(bf[nj*2][0]), "=r"(bf[nj*2][1]),
                               "=r"(bf[nj*2+1][0]), "=r"(bf[nj*2+1][1]) : "r"(bd));
            }
            #pragma unroll
            for (int mi = 0; mi < 4; mi++)
                #pragma unroll
                for (int ni = 0; ni < 4; ni++) {
                    float* d = acc[mi][ni];
                    asm volatile(
                        "mma.sync.aligned.m16n8k16.row.col.f32.f16.f16.f32 "
                        "{%0,%1,%2,%3},{%4,%5,%6,%7},{%8,%9},{%0,%1,%2,%3};"
                        : "+f"(d[0]), "+f"(d[1]), "+f"(d[2]), "+f"(d[3])
                        : "r"(af[mi][0]), "r"(af[mi][1]), "r"(af[mi][2]), "r"(af[mi][3]),
                          "r"(bf[ni][0]), "r"(bf[ni][1]));
                }
        }
        // no trailing sync: 3-stage ring, next fill target fenced by next-iter barrier
    }

    // ---- epilogue ----
    #pragma unroll
    for (int mi = 0; mi < 4; mi++) {
        int r0 = m0 + wm * 64 + mi * 16 + grp;
        int r1 = r0 + 8;
        int dst0 = 0, dst1 = 0;
        if (MODE == 1) { dst0 = winrow_to_dst(r0); dst1 = winrow_to_dst(r1); }
        #pragma unroll
        for (int ni = 0; ni < 4; ni++) {
            int col = n0 + wn * 32 + ni * 8 + tig * 2;
            float b0 = bias[col], b1 = bias[col + 1];
            float v00 = acc[mi][ni][0] + b0, v01 = acc[mi][ni][1] + b1;
            float v10 = acc[mi][ni][2] + b0, v11 = acc[mi][ni][3] + b1;
            if (MODE == 0) {
                *(__half2*)&Ch[(size_t)r0 * N + col] = __floats2half2_rn(v00, v01);
                *(__half2*)&Ch[(size_t)r1 * N + col] = __floats2half2_rn(v10, v11);
            } else if (MODE == 1) {
                size_t o0 = (size_t)dst0 * CCH + col;
                size_t o1 = (size_t)dst1 * CCH + col;
                *(float2*)&Cf[o0] = make_float2(resid[o0] + v00, resid[o0 + 1] + v01);
                *(float2*)&Cf[o1] = make_float2(resid[o1] + v10, resid[o1 + 1] + v11);
            } else if (MODE == 2) {
                const float is2 = 0.70710678118654752f;
                v00 = 0.5f * v00 * (1.0f + erff(v00 * is2));
                v01 = 0.5f * v01 * (1.0f + erff(v01 * is2));
                v10 = 0.5f * v10 * (1.0f + erff(v10 * is2));
                v11 = 0.5f * v11 * (1.0f + erff(v11 * is2));
                *(__half2*)&Ch[(size_t)r0 * N + col] = __floats2half2_rn(v00, v01);
                *(__half2*)&Ch[(size_t)r1 * N + col] = __floats2half2_rn(v10, v11);
            } else {
                size_t o0 = (size_t)r0 * CCH + col;
                size_t o1 = (size_t)r1 * CCH + col;
                *(float2*)&Cf[o0] = make_float2(resid[o0] + v00, resid[o0 + 1] + v01);
                *(float2*)&Cf[o1] = make_float2(resid[o1] + v10, resid[o1 + 1] + v11);
            }
        }
    }
}

// ---------------- MMA windowed attention: one block per (window, head) -------
__global__ void __launch_bounds__(128)
attn_kernel(const __half* __restrict__ qkv, const float* __restrict__ rpb,
            __half* __restrict__ out)
{
    __shared__ __align__(16) unsigned char sm[15360 + 64 * 56 * 4];
    __shared__ int regio[49];

    __half* Qh = (__half*)sm;                 // [64][40]
    __half* Kh = (__half*)(sm + 5120);        // [64][40]
    __half* Vh = (__half*)(sm + 10240);       // [64][40]
    __half* Ph = (__half*)sm;                 // [64][72] alias over Qh+Kh
    float*  S  = (float*)(sm + 15360);        // [64][56]

    int blk  = blockIdx.x;
    int head = blk % NHEAD;
    int win  = blk / NHEAD;
    int tid  = threadIdx.x;
    int wid  = tid >> 5, lane = tid & 31;
    int grp  = lane >> 2, tig = lane & 3;
    const float scale = 0.17677669529663687f;   // 32^-0.5

    // ---- load Q/K/V (fp16 half2), zero V pad rows ----
    {
        const __half2* q2 = (const __half2*)(qkv + (size_t)win * 49 * HID3 + head * 32);
        __half2* Q2 = (__half2*)Qh;  __half2* K2 = (__half2*)Kh;  __half2* V2 = (__half2*)Vh;
        for (int idx = tid; idx < 49 * 16; idx += 128) {
            int n = idx >> 4, c = idx & 15;
            const __half2* row = q2 + (size_t)n * (HID3 / 2);
            Q2[n * 20 + c] = row[c];
            K2[n * 20 + c] = row[c + 192];
            V2[n * 20 + c] = row[c + 384];
        }
        for (int idx = tid; idx < 15 * 16; idx += 128) {
            int n = 49 + (idx >> 4), c = idx & 15;
            V2[n * 20 + c] = __half2half2(__float2half(0.0f));
        }
        if (tid < 49) {
            int nw = win & 63;
            int wh = nw >> 3, ww = nw & 7;
            int r = tid / 7, c = tid % 7;
            int hh = wh * 7 + r, wg = ww * 7 + c;
            int rh = hh < 49 ? 0 : (hh < 53 ? 1 : 2);
            int rw = wg < 49 ? 0 : (wg < 53 ? 1 : 2);
            regio[tid] = rh * 3 + rw;
        }
    }
    __syncthreads();

    uint32_t sQ = (uint32_t)__cvta_generic_to_shared(Qh);
    uint32_t sK = (uint32_t)__cvta_generic_to_shared(Kh);
    uint32_t sV = (uint32_t)__cvta_generic_to_shared(Vh);
    uint32_t sP = (uint32_t)__cvta_generic_to_shared(Ph);

    // ---- S = Q K^T (M=64, N=56, K=32) ----
    {
        float acc[7][4];
        #pragma unroll
        for (int ni = 0; ni < 7; ni++)
            #pragma unroll
            for (int r = 0; r < 4; r++) acc[ni][r] = 0.0f;

        uint32_t aoff = (uint32_t)((wid * 16 + (lane & 15)) * 80 + ((lane >> 4) << 4));
        uint32_t boff = (uint32_t)((((lane >> 4) << 3) + (lane & 7)) * 80
                                   + (((lane >> 3) & 1) << 4));
        #pragma unroll
        for (int ks = 0; ks < 2; ks++) {
            uint32_t af[4], bf[8][2];
            asm volatile("ldmatrix.sync.aligned.m8n8.x4.shared.b16 {%0,%1,%2,%3},[%4];"
                         : "=r"(af[0]), "=r"(af[1]), "=r"(af[2]), "=r"(af[3])
                         : "r"(sQ + aoff + ks * 32));
            #pragma unroll
            for (int nj = 0; nj < 4; nj++) {
                uint32_t bd = sK + boff + (uint32_t)(nj * 16 * 80 + ks * 32);
                asm volatile("ldmatrix.sync.aligned.m8n8.x4.shared.b16 {%0,%1,%2,%3},[%4];"
                             : "=r"(bf[nj*2][0]), "=r"(bf[nj*2][1]),
                               "=r"(bf[nj*2+1][0]), "=r"(bf[nj*2+1][1]) : "r"(bd));
            }
            #pragma unroll
            for (int ni = 0; ni < 7; ni++) {
                float* d = acc[ni];
                asm volatile(
                    "mma.sync.aligned.m16n8k16.row.col.f32.f16.f16.f32 "
                    "{%0,%1,%2,%3},{%4,%5,%6,%7},{%8,%9},{%0,%1,%2,%3};"
                    : "+f"(d[0]), "+f"(d[1]), "+f"(d[2]), "+f"(d[3])
                    : "r"(af[0]), "r"(af[1]), "r"(af[2]), "r"(af[3]),
                      "r"(bf[ni][0]), "r"(bf[ni][1]));
            }
        }

        int r0 = wid * 16 + grp, r1 = r0 + 8;
        #pragma unroll
        for (int ni = 0; ni < 7; ni++) {
            int c = ni * 8 + tig * 2;
            #pragma unroll
            for (int e = 0; e < 4; e++) {
                int i = (e < 2) ? r0 : r1;
                int j = c + (e & 1);
                if (i < 49 && j < 49) {
                    int ri = i / 7, ci = i % 7, rj = j / 7, cj = j % 7;
                    float s = acc[ni][e] * scale
                            + rpb[((ri - rj + 6) * 13 + (ci - cj + 6)) * NHEAD + head];
                    if (regio[i] != regio[j]) s -= 100.0f;
                    S[i * 56 + j] = s;
                }
            }
        }
    }
    __syncthreads();

    // ---- zero Ph (aliases Qh/Kh), then softmax rows -> Ph fp16 ----
    {
        __half2* P2 = (__half2*)Ph;
        for (int idx = tid; idx < 64 * 36; idx += 128)
            P2[idx] = __half2half2(__float2half(0.0f));
    }
    __syncthreads();
    for (int i = wid; i < 49; i += 4) {
        float v0 = S[i * 56 + lane];
        float v1 = (lane + 32 < 49) ? S[i * 56 + lane + 32] : -1e30f;
        float m = fmaxf(v0, v1);
        #pragma unroll
        for (int o = 16; o; o >>= 1) m = fmaxf(m, __shfl_xor_sync(0xffffffffu, m, o));
        float e0 = __expf(v0 - m);
        float e1 = (lane + 32 < 49) ? __expf(v1 - m) : 0.0f;
        float sum = e0 + e1;
        #pragma unroll
        for (int o = 16; o; o >>= 1) sum += __shfl_xor_sync(0xffffffffu, sum, o);
        float inv = 1.0f / sum;
        Ph[i * 72 + lane] = __float2half(e0 * inv);
        if (lane + 32 < 49) Ph[i * 72 + lane + 32] = __float2half(e1 * inv);
    }
    __syncthreads();

    // ---- O = P V  (M=64, N=32, K=64) ----
    {
        float acc[4][4];
        #pragma unroll
        for (int ni = 0; ni < 4; ni++)
            #pragma unroll
            for (int r = 0; r < 4; r++) acc[ni][r] = 0.0f;

        uint32_t aoff = (uint32_t)((wid * 16 + (lane & 15)) * 144 + ((lane >> 4) << 4));
        uint32_t voff = (uint32_t)((lane & 15) * 80 + ((lane >> 4) << 4));
        #pragma unroll
        for (int ks = 0; ks < 4; ks++) {
            uint32_t af[4], bf[4][2];
            asm volatile("ldmatrix.sync.aligned.m8n8.x4.shared.b16 {%0,%1,%2,%3},[%4];"
                         : "=r"(af[0]), "=r"(af[1]), "=r"(af[2]), "=r"(af[3])
                         : "r"(sP + aoff + ks * 32));
            #pragma unroll
            for (int np = 0; np < 2; np++) {
                uint32_t bd = sV + voff + (uint32_t)(ks * 16 * 80 + np * 32);
                asm volatile("ldmatrix.sync.aligned.m8n8.x4.trans.shared.b16 {%0,%1,%2,%3},[%4];"
                             : "=r"(bf[np*2][0]), "=r"(bf[np*2][1]),
                               "=r"(bf[np*2+1][0]), "=r"(bf[np*2+1][1]) : "r"(bd));
            }
            #pragma unroll
            for (int ni = 0; ni < 4; ni++) {
                float* d = acc[ni];
                asm volatile(
                    "mma.sync.aligned.m16n8k16.row.col.f32.f16.f16.f32 "
                    "{%0,%1,%2,%3},{%4,%5,%6,%7},{%8,%9},{%0,%1,%2,%3};"
                    : "+f"(d[0]), "+f"(d[1]), "+f"(d[2]), "+f"(d[3])
                    : "r"(af[0]), "r"(af[1]), "r"(af[2]), "r"(af[3]),
                      "r"(bf[ni][0]), "r"(bf[ni][1]));
            }
        }

        int r0 = wid * 16 + grp, r1 = r0 + 8;
        #pragma unroll
        for (int ni = 0; ni < 4; ni++) {
            int d = ni * 8 + tig * 2;
            if (r0 < 49)
                *(__half2*)&out[((size_t)win * 49 + r0) * CCH + head * 32 + d] =
                    __floats2half2_rn(acc[ni][0], acc[ni][1]);
            if (r1 < 49)
                *(__half2*)&out[((size_t)win * 49 + r1) * CCH + head * 32 + d] =
                    __floats2half2_rn(acc[ni][2], acc[ni][3]);
        }
    }
}

// ---------------------------------- driver -----------------------------------
extern "C" void kernel_launch(void* const* d_in, const int* in_sizes, int n_in,
                              void* d_out, int out_size)
{
    const float* x      = (const float*)d_in[0];
    const float* g1     = (const float*)d_in[1];
    const float* b1     = (const float*)d_in[2];
    const float* w_qkv  = (const float*)d_in[3];
    const float* b_qkv  = (const float*)d_in[4];
    const float* w_proj = (const float*)d_in[5];
    const float* b_proj = (const float*)d_in[6];
    const float* rpb    = (const float*)d_in[7];
    const float* g2     = (const float*)d_in[8];
    const float* b2     = (const float*)d_in[9];
    const float* w1     = (const float*)d_in[10];
    const float* bm1    = (const float*)d_in[11];
    const float* w2     = (const float*)d_in[12];
    const float* bm2    = (const float*)d_in[13];
    float* out = (float*)d_out;

    __half *h, *big, *wT;
    float *y;
    cudaGetSymbolAddress((void**)&h,   g_h);
    cudaGetSymbolAddress((void**)&big, g_big);
    cudaGetSymbolAddress((void**)&y,   g_y);
    cudaGetSymbolAddress((void**)&wT,  g_wT);

    cudaFuncSetAttribute(gemm_h<0>, cudaFuncAttributeMaxDynamicSharedMemorySize, GH_SMEM);
    cudaFuncSetAttribute(gemm_h<1>, cudaFuncAttributeMaxDynamicSharedMemorySize, GH_SMEM);
    cudaFuncSetAttribute(gemm_h<2>, cudaFuncAttributeMaxDynamicSharedMemorySize, GH_SMEM);
    cudaFuncSetAttribute(gemm_h<3>, cudaFuncAttributeMaxDynamicSharedMemorySize, GH_SMEM);

    // 0) transpose + cvt weights -> fp16 [N, K]
    transpose_kernel<<<dim3(HID3 / 32, CCH / 32), 256>>>(w_qkv,  wT + OFF_QKVT,  CCH,  HID3);
    transpose_kernel<<<dim3(CCH  / 32, CCH / 32), 256>>>(w_proj, wT + OFF_PROJT, CCH,  CCH);
    transpose_kernel<<<dim3(HIDM / 32, CCH / 32), 256>>>(w1,     wT + OFF_W1T,   CCH,  HIDM);
    transpose_kernel<<<dim3(CCH / 32, HIDM / 32), 256>>>(w2,     wT + OFF_W2T,   HIDM, CCH);

    // 1) LN1 + roll(-3,-3) + window partition -> h fp16 [100352, 384]
    ln_kernel<<<TOK, 128>>>(x, g1, b1, h, 1);

    // 2) QKV: h @ w_qkv + b_qkv -> big fp16 [100352, 1152]
    gemm_h<0><<<dim3(HID3 / 128, TOK / 128), 256, GH_SMEM>>>(
        h, wT + OFF_QKVT, big, b_qkv, nullptr, TOK, HID3, CCH);

    // 3) attention per (window, head) -> h fp16 [100352, 384]
    attn_kernel<<<NWIN * NHEAD, 128>>>(big, rpb, h);

    // 4) proj + window reverse + roll(+3,+3) + residual(x) -> y fp32
    gemm_h<1><<<dim3(CCH / 128, TOK / 128), 256, GH_SMEM>>>(
        h, wT + OFF_PROJT, y, b_proj, x, TOK, CCH, CCH);

    // 5) LN2 -> h fp16
    ln_kernel<<<TOK, 128>>>(y, g2, b2, h, 0);

    // 6) fc1 + exact GELU -> big fp16 [100352, 1536]
    gemm_h<2><<<dim3(HIDM / 128, TOK / 128), 256, GH_SMEM>>>(
        h, wT + OFF_W1T, big, bm1, nullptr, TOK, HIDM, CCH);

    // 7) fc2 + residual(y) -> out fp32
    gemm_h<3><<<dim3(CCH / 128, TOK / 128), 256, GH_SMEM>>>(
        big, wT + OFF_W2T, out, bm2, y, TOK, CCH, HIDM);
}